// round 6
// baseline (speedup 1.0000x reference)
#include <cuda_runtime.h>
#include <cuda_bf16.h>
#include <cstddef>
#include <cstdint>

#define WB     1024
#define NTOK   128
#define NHEADS 8
#define HD     16
#define MROWS  (WB * NTOK)          // 131072

typedef unsigned long long ull;

// ---------------- scratch (device globals; no runtime allocation) ----------
__device__ unsigned short g_xs3  [(size_t)MROWS * 384];   // x,   K'=384
__device__ unsigned short g_xpes3[(size_t)MROWS * 384];   // x+pe K'=384
__device__ unsigned short g_ws3  [384 * 384];             // w_self
__device__ unsigned short g_wm3  [384 * 384];             // w_mut
__device__ unsigned short g_wp3  [128 * 768];             // w_proj K'=768
__device__ float g_qkv_self[(size_t)MROWS * 384];
__device__ float g_qkv_mut [(size_t)MROWS * 384];
__device__ unsigned short g_concat3[(size_t)MROWS * 768]; // [row][col*3]
__device__ float g_biasT[NHEADS * NTOK * NTOK];           // [h][m][i]
__device__ float g_maskT[512 * NTOK * NTOK];              // [w][m][i]

__device__ __forceinline__ void split_hl(float v, unsigned short& h, unsigned short& l) {
    __nv_bfloat16 hh = __float2bfloat16(v);
    float r = v - __bfloat162float(hh);
    __nv_bfloat16 ll = __float2bfloat16(r);
    h = *(unsigned short*)&hh;
    l = *(unsigned short*)&ll;
}

// ---------------- f32x2 packed math ----------------------------------------
#define FMA2(d, a, b) asm("fma.rn.f32x2 %0, %1, %2, %0;" : "+l"(d) : "l"(a), "l"(b))
#define ADD2(d, a, b) asm("add.rn.f32x2 %0, %1, %2;" : "=l"(d) : "l"(a), "l"(b))
#define MUL2(d, a, b) asm("mul.rn.f32x2 %0, %1, %2;" : "=l"(d) : "l"(a), "l"(b))
#define PACKF2(d, lo, hi) asm("mov.b64 %0, {%1, %2};" : "=l"(d) : "f"(lo), "f"(hi))
#define UNPACKF2(lo, hi, s) asm("mov.b64 {%0, %1}, %2;" : "=f"(lo), "=f"(hi) : "l"(s))

// ---------------- prep kernels ---------------------------------------------
__global__ void wsplit_all(const float* __restrict__ ws, const float* __restrict__ wm,
                           const float* __restrict__ wp)
{
    int i = blockIdx.x * 256 + threadIdx.x;     // 0 .. 131071
    float v; unsigned short* dst;
    if (i < 49152)       { v = ws[i];          dst = g_ws3 + 3 * i; }
    else if (i < 98304)  { v = wm[i - 49152];  dst = g_wm3 + 3 * (i - 49152); }
    else                 { v = wp[i - 98304];  dst = g_wp3 + 3 * (i - 98304); }
    unsigned short h, l;
    split_hl(v, h, l);
    dst[0] = h; dst[1] = l; dst[2] = h;
}

__global__ void xprep(const float* __restrict__ x, const float* __restrict__ pe)
{
    size_t idx8 = (size_t)blockIdx.x * 256 + threadIdx.x;
    size_t e0 = idx8 * 8;
    int c = (int)(e0 & 127);
    int t = (int)((e0 >> 7) & 127);
    float4 xv0 = ((const float4*)x)[idx8 * 2];
    float4 xv1 = ((const float4*)x)[idx8 * 2 + 1];
    const float* pp = pe + (t & 63) * 128 + c;
    float xe[8] = {xv0.x, xv0.y, xv0.z, xv0.w, xv1.x, xv1.y, xv1.z, xv1.w};

    unsigned short b0[24], b1[24];
#pragma unroll
    for (int j = 0; j < 8; ++j) {
        unsigned short h, l;
        split_hl(xe[j], h, l);
        b0[3 * j] = h; b0[3 * j + 1] = h; b0[3 * j + 2] = l;
        split_hl(xe[j] + pp[j], h, l);
        b1[3 * j] = h; b1[3 * j + 1] = h; b1[3 * j + 2] = l;
    }
    uint4* d0 = (uint4*)(g_xs3 + 3 * e0);
    uint4* d1 = (uint4*)(g_xpes3 + 3 * e0);
    const uint4* s0 = (const uint4*)b0;
    const uint4* s1 = (const uint4*)b1;
    d0[0] = s0[0]; d0[1] = s0[1]; d0[2] = s0[2];
    d1[0] = s1[0]; d1[1] = s1[1]; d1[2] = s1[2];
}

// fused: maskT transpose (z < 512) + biasT gather (z == 512)
__global__ void prep_misc(const float* __restrict__ mask,
                          const int* __restrict__ rpe_index,
                          const float* __restrict__ rpe_table)
{
    int tx = threadIdx.x, ty = threadIdx.y;         // 32 x 8
    if (blockIdx.z == 512) {
        int blin = blockIdx.y * 4 + blockIdx.x;     // 0..15
        int tid0 = blin * 256 + ty * 32 + tx;       // 0..4095
#pragma unroll
        for (int j = 0; j < 4; ++j) {
            int tid = tid0 + j * 4096;              // tid = m*128 + i
            int i = tid & 127, m = tid >> 7;
            int t = rpe_index[i * 128 + m];
#pragma unroll
            for (int h = 0; h < NHEADS; ++h)
                g_biasT[h * 16384 + tid] = rpe_table[t * NHEADS + h];
        }
        return;
    }
    __shared__ float tile[32][33];
    int w = blockIdx.z;
    int x0 = blockIdx.x * 32, y0 = blockIdx.y * 32;
    const float* src = mask + (size_t)w * 16384;
    float* dst = g_maskT + (size_t)w * 16384;
#pragma unroll
    for (int j = 0; j < 32; j += 8)
        tile[ty + j][tx] = src[(y0 + ty + j) * 128 + x0 + tx];
    __syncthreads();
#pragma unroll
    for (int j = 0; j < 32; j += 8)
        dst[(x0 + ty + j) * 128 + y0 + tx] = tile[tx][ty + j];
}

// ---------------- bf16-split tensor-core GEMM ------------------------------
#define MMA_BF16(d, a, b0r, b1r) \
    asm volatile("mma.sync.aligned.m16n8k16.row.col.f32.bf16.bf16.f32 " \
        "{%0,%1,%2,%3},{%4,%5,%6,%7},{%8,%9},{%0,%1,%2,%3};" \
        : "+f"(d[0]), "+f"(d[1]), "+f"(d[2]), "+f"(d[3]) \
        : "r"(a[0]), "r"(a[1]), "r"(a[2]), "r"(a[3]), "r"(b0r), "r"(b1r))

#define LDSM4(r0, r1, r2, r3, addr) \
    asm volatile("ldmatrix.sync.aligned.m8n8.x4.shared.b16 {%0,%1,%2,%3}, [%4];" \
        : "=r"(r0), "=r"(r1), "=r"(r2), "=r"(r3) : "r"(addr))

#define CP16(dst, src) \
    asm volatile("cp.async.cg.shared.global [%0], [%1], 16;" :: "r"(dst), "l"(src))

#define PITCH 72
#define STAGE_ELEMS (128 * PITCH)

template<int KTOT, int NTOT, bool BIAS>
__global__ void __launch_bounds__(256) gemm_bf16(
    const __nv_bfloat16* __restrict__ A, const __nv_bfloat16* __restrict__ W,
    const float* __restrict__ bvec, float* __restrict__ C)
{
    extern __shared__ __nv_bfloat16 smem[];
    __nv_bfloat16* As = smem;                        // [2][128*72]
    __nv_bfloat16* Bs = smem + 2 * STAGE_ELEMS;      // [2][128*72]

    const int tid = threadIdx.x;
    const int lane = tid & 31, wid = tid >> 5;
    const int wm = (wid & 1) * 64, wn = (wid >> 1) * 32;
    const int g = lane >> 2, tg = lane & 3;
    const size_t row0 = (size_t)blockIdx.y * 128;
    const int col0 = blockIdx.x * 128;
    constexpr int NC = KTOT / 64;

    const int ldr = tid >> 1;
    const int ldu = (tid & 1) * 4;

    float acc[4][4][4] = {};

    const int a_row = wm + (lane & 15);
    const int a_col = (lane >> 4) * 8;
    const int bq = lane >> 3;
    const int b_row = wn + ((bq >> 1) * 8) + (lane & 7);
    const int b_col = (bq & 1) * 8;

#define LOAD_STAGE(kc, s)                                                        \
    {                                                                            \
        const __nv_bfloat16* Ab = A + (row0 + ldr) * KTOT + (kc) * 64;           \
        const __nv_bfloat16* Wb = W + (size_t)(col0 + ldr) * KTOT + (kc) * 64;   \
        __nv_bfloat16* Ad = As + (s) * STAGE_ELEMS + ldr * PITCH;                \
        __nv_bfloat16* Bd = Bs + (s) * STAGE_ELEMS + ldr * PITCH;                \
        _Pragma("unroll")                                                        \
        for (int u = 0; u < 4; ++u) {                                            \
            unsigned da = (unsigned)__cvta_generic_to_shared(Ad + (ldu + u) * 8);\
            CP16(da, Ab + (ldu + u) * 8);                                        \
            unsigned db = (unsigned)__cvta_generic_to_shared(Bd + (ldu + u) * 8);\
            CP16(db, Wb + (ldu + u) * 8);                                        \
        }                                                                        \
        asm volatile("cp.async.commit_group;");                                  \
    }

    LOAD_STAGE(0, 0);

    for (int kc = 0; kc < NC; ++kc) {
        if (kc + 1 < NC) {
            LOAD_STAGE(kc + 1, (kc + 1) & 1);
            asm volatile("cp.async.wait_group 1;");
        } else {
            asm volatile("cp.async.wait_group 0;");
        }
        __syncthreads();

        const __nv_bfloat16* Ad = As + (kc & 1) * STAGE_ELEMS;
        const __nv_bfloat16* Bd = Bs + (kc & 1) * STAGE_ELEMS;
#pragma unroll
        for (int ks = 0; ks < 4; ++ks) {
            const int kb = ks * 16;
            uint32_t a[4][4], b[2][4];
#pragma unroll
            for (int mt = 0; mt < 4; ++mt) {
                unsigned ad = (unsigned)__cvta_generic_to_shared(
                    Ad + (a_row + mt * 16) * PITCH + kb + a_col);
                LDSM4(a[mt][0], a[mt][1], a[mt][2], a[mt][3], ad);
            }
#pragma unroll
            for (int p = 0; p < 2; ++p) {
                unsigned bd = (unsigned)__cvta_generic_to_shared(
                    Bd + (b_row + p * 16) * PITCH + kb + b_col);
                LDSM4(b[p][0], b[p][1], b[p][2], b[p][3], bd);
            }
#pragma unroll
            for (int mt = 0; mt < 4; ++mt)
#pragma unroll
                for (int nt = 0; nt < 4; ++nt)
                    MMA_BF16(acc[mt][nt], a[mt], b[nt >> 1][(nt & 1) * 2],
                             b[nt >> 1][(nt & 1) * 2 + 1]);
        }
        __syncthreads();
    }

#pragma unroll
    for (int mt = 0; mt < 4; ++mt) {
#pragma unroll
        for (int nt = 0; nt < 4; ++nt) {
            size_t row = row0 + wm + mt * 16 + g;
            int col = col0 + wn + nt * 8 + 2 * tg;
            float b0 = BIAS ? bvec[col] : 0.f, b1 = BIAS ? bvec[col + 1] : 0.f;
            *(float2*)&C[row * NTOT + col] =
                make_float2(acc[mt][nt][0] + b0, acc[mt][nt][1] + b1);
            *(float2*)&C[(row + 8) * NTOT + col] =
                make_float2(acc[mt][nt][2] + b0, acc[mt][nt][3] + b1);
        }
    }
}

// ---------------- write attention output as A-side triplets -----------------
__device__ __forceinline__ void store_triplets16(unsigned short* dst, const float* v)
{
    unsigned short ob[48];
#pragma unroll
    for (int c = 0; c < 16; ++c) {
        unsigned short h, l;
        split_hl(v[c], h, l);
        ob[3 * c] = h; ob[3 * c + 1] = h; ob[3 * c + 2] = l;
    }
    uint4* d = (uint4*)dst;
    const uint4* s = (const uint4*)ob;
#pragma unroll
    for (int j = 0; j < 6; ++j) d[j] = s[j];
}

// ---------------- self attention: 64 thr, 2 queries/thread, f32x2 ----------
__global__ void __launch_bounds__(64) attn_self()
{
    const int b = blockIdx.x, h = blockIdx.y, t = threadIdx.x;
    __shared__ ulonglong2 ks[NTOK * 4];
    __shared__ ulonglong2 vs[NTOK * 4];
    const float* base = g_qkv_self + (size_t)b * NTOK * 384;

#pragma unroll
    for (int rr = 0; rr < 2; ++rr) {
        int r = t + rr * 64;
        const ulonglong2* kr = (const ulonglong2*)(base + r * 384 + 128 + h * HD);
        const ulonglong2* vr = (const ulonglong2*)(base + r * 384 + 256 + h * HD);
#pragma unroll
        for (int j = 0; j < 4; ++j) { ks[r * 4 + j] = kr[j]; vs[r * 4 + j] = vr[j]; }
    }
    const ull C025 = 0x3E8000003E800000ull;          // (0.25f, 0.25f)
    ull qa[8], qb[8];
    {
        const ull* q0 = (const ull*)(base + t * 384 + h * HD);
        const ull* q1 = (const ull*)(base + (t + 64) * 384 + h * HD);
#pragma unroll
        for (int j = 0; j < 8; ++j) { MUL2(qa[j], q0[j], C025); MUL2(qb[j], q1[j], C025); }
    }
    __syncthreads();

    const float* ma = g_maskT + (size_t)(b & 511) * 16384 + t;
    const float* mb = ma + 64;
    const float* ba = g_biasT + h * 16384 + t;
    const float* bb = ba + 64;

    ull acca[8] = {}, accb[8] = {};
    float sma = 0.f, smb = 0.f;
#pragma unroll 2
    for (int m = 0; m < NTOK; ++m) {
        ulonglong2 k0 = ks[m * 4 + 0], k1 = ks[m * 4 + 1];
        ulonglong2 k2 = ks[m * 4 + 2], k3 = ks[m * 4 + 3];
        ull da0 = 0, da1 = 0, db0 = 0, db1 = 0;
        FMA2(da0, qa[0], k0.x); FMA2(da1, qa[1], k0.y);
        FMA2(da0, qa[2], k1.x); FMA2(da1, qa[3], k1.y);
        FMA2(da0, qa[4], k2.x); FMA2(da1, qa[5], k2.y);
        FMA2(da0, qa[6], k3.x); FMA2(da1, qa[7], k3.y);
        FMA2(db0, qb[0], k0.x); FMA2(db1, qb[1], k0.y);
        FMA2(db0, qb[2], k1.x); FMA2(db1, qb[3], k1.y);
        FMA2(db0, qb[4], k2.x); FMA2(db1, qb[5], k2.y);
        FMA2(db0, qb[6], k3.x); FMA2(db1, qb[7], k3.y);
        ull ds; float lo, hi;
        ADD2(ds, da0, da1); UNPACKF2(lo, hi, ds);
        float sa = lo + hi + ma[m * 128] + ba[m * 128];
        ADD2(ds, db0, db1); UNPACKF2(lo, hi, ds);
        float sb = lo + hi + mb[m * 128] + bb[m * 128];
        float pa = __expf(sa), pb = __expf(sb);
        sma += pa; smb += pb;
        ull pa2, pb2; PACKF2(pa2, pa, pa); PACKF2(pb2, pb, pb);
        ulonglong2 v0 = vs[m * 4 + 0], v1 = vs[m * 4 + 1];
        ulonglong2 v2 = vs[m * 4 + 2], v3 = vs[m * 4 + 3];
        FMA2(acca[0], pa2, v0.x); FMA2(acca[1], pa2, v0.y);
        FMA2(acca[2], pa2, v1.x); FMA2(acca[3], pa2, v1.y);
        FMA2(acca[4], pa2, v2.x); FMA2(acca[5], pa2, v2.y);
        FMA2(acca[6], pa2, v3.x); FMA2(acca[7], pa2, v3.y);
        FMA2(accb[0], pb2, v0.x); FMA2(accb[1], pb2, v0.y);
        FMA2(accb[2], pb2, v1.x); FMA2(accb[3], pb2, v1.y);
        FMA2(accb[4], pb2, v2.x); FMA2(accb[5], pb2, v2.y);
        FMA2(accb[6], pb2, v3.x); FMA2(accb[7], pb2, v3.y);
    }
    float ia = 1.f / sma, ib = 1.f / smb;
    float oa[16], ob[16];
#pragma unroll
    for (int j = 0; j < 8; ++j) {
        float lo, hi;
        UNPACKF2(lo, hi, acca[j]); oa[2 * j] = lo * ia; oa[2 * j + 1] = hi * ia;
        UNPACKF2(lo, hi, accb[j]); ob[2 * j] = lo * ib; ob[2 * j + 1] = hi * ib;
    }
    store_triplets16(g_concat3 + ((size_t)b * NTOK + t) * 768 + (128 + h * HD) * 3, oa);
    store_triplets16(g_concat3 + ((size_t)b * NTOK + t + 64) * 768 + (128 + h * HD) * 3, ob);
}

// ---------------- mutual cross attention -----------------------------------
// out token t     = query(64+t) over keys[0:64)
// out token t+64  = query(t)    over keys[64:128)   (same mask element)
__global__ void __launch_bounds__(64) attn_mut()
{
    const int b = blockIdx.x, h = blockIdx.y, t = threadIdx.x;
    __shared__ ulonglong2 ks[NTOK * 4];
    __shared__ ulonglong2 vs[NTOK * 4];
    const float* base = g_qkv_mut + (size_t)b * NTOK * 384;

#pragma unroll
    for (int rr = 0; rr < 2; ++rr) {
        int r = t + rr * 64;
        const ulonglong2* kr = (const ulonglong2*)(base + r * 384 + 128 + h * HD);
        const ulonglong2* vr = (const ulonglong2*)(base + r * 384 + 256 + h * HD);
#pragma unroll
        for (int j = 0; j < 4; ++j) { ks[r * 4 + j] = kr[j]; vs[r * 4 + j] = vr[j]; }
    }
    const ull C025 = 0x3E8000003E800000ull;
    ull qa[8], qb[8];
    {
        const ull* q0 = (const ull*)(base + (64 + t) * 384 + h * HD);
        const ull* q1 = (const ull*)(base + t * 384 + h * HD);
#pragma unroll
        for (int j = 0; j < 8; ++j) { MUL2(qa[j], q0[j], C025); MUL2(qb[j], q1[j], C025); }
    }
    __syncthreads();

    const float* mk = g_maskT + (size_t)(b & 511) * 16384 + t;

    ull acca[8] = {}, accb[8] = {};
    float sma = 0.f, smb = 0.f;
#pragma unroll 2
    for (int m = 0; m < 64; ++m) {
        ulonglong2 ka0 = ks[m * 4 + 0], ka1 = ks[m * 4 + 1];
        ulonglong2 ka2 = ks[m * 4 + 2], ka3 = ks[m * 4 + 3];
        ulonglong2 kb0 = ks[(64 + m) * 4 + 0], kb1 = ks[(64 + m) * 4 + 1];
        ulonglong2 kb2 = ks[(64 + m) * 4 + 2], kb3 = ks[(64 + m) * 4 + 3];
        ull da0 = 0, da1 = 0, db0 = 0, db1 = 0;
        FMA2(da0, qa[0], ka0.x); FMA2(da1, qa[1], ka0.y);
        FMA2(da0, qa[2], ka1.x); FMA2(da1, qa[3], ka1.y);
        FMA2(da0, qa[4], ka2.x); FMA2(da1, qa[5], ka2.y);
        FMA2(da0, qa[6], ka3.x); FMA2(da1, qa[7], ka3.y);
        FMA2(db0, qb[0], kb0.x); FMA2(db1, qb[1], kb0.y);
        FMA2(db0, qb[2], kb1.x); FMA2(db1, qb[3], kb1.y);
        FMA2(db0, qb[4], kb2.x); FMA2(db1, qb[5], kb2.y);
        FMA2(db0, qb[6], kb3.x); FMA2(db1, qb[7], kb3.y);
        float mv = mk[m * 128];
        ull ds; float lo, hi;
        ADD2(ds, da0, da1); UNPACKF2(lo, hi, ds);
        float sa = lo + hi + mv;
        ADD2(ds, db0, db1); UNPACKF2(lo, hi, ds);
        float sb = lo + hi + mv;
        float pa = __expf(sa), pb = __expf(sb);
        sma += pa; smb += pb;
        ull pa2, pb2; PACKF2(pa2, pa, pa); PACKF2(pb2, pb, pb);
        ulonglong2 va0 = vs[m * 4 + 0], va1 = vs[m * 4 + 1];
        ulonglong2 va2 = vs[m * 4 + 2], va3 = vs[m * 4 + 3];
        ulonglong2 vb0 = vs[(64 + m) * 4 + 0], vb1 = vs[(64 + m) * 4 + 1];
        ulonglong2 vb2 = vs[(64 + m) * 4 + 2], vb3 = vs[(64 + m) * 4 + 3];
        FMA2(acca[0], pa2, va0.x); FMA2(acca[1], pa2, va0.y);
        FMA2(acca[2], pa2, va1.x); FMA2(acca[3], pa2, va1.y);
        FMA2(acca[4], pa2, va2.x); FMA2(acca[5], pa2, va2.y);
        FMA2(acca[6], pa2, va3.x); FMA2(acca[7], pa2, va3.y);
        FMA2(accb[0], pb2, vb0.x); FMA2(accb[1], pb2, vb0.y);
        FMA2(accb[2], pb2, vb1.x); FMA2(accb[3], pb2, vb1.y);
        FMA2(accb[4], pb2, vb2.x); FMA2(accb[5], pb2, vb2.y);
        FMA2(accb[6], pb2, vb3.x); FMA2(accb[7], pb2, vb3.y);
    }
    float ia = 1.f / sma, ib = 1.f / smb;
    float oa[16], ob[16];
#pragma unroll
    for (int j = 0; j < 8; ++j) {
        float lo, hi;
        UNPACKF2(lo, hi, acca[j]); oa[2 * j] = lo * ia; oa[2 * j + 1] = hi * ia;
        UNPACKF2(lo, hi, accb[j]); ob[2 * j] = lo * ib; ob[2 * j + 1] = hi * ib;
    }
    store_triplets16(g_concat3 + ((size_t)b * NTOK + t) * 768 + (h * HD) * 3, oa);
    store_triplets16(g_concat3 + ((size_t)b * NTOK + t + 64) * 768 + (h * HD) * 3, ob);
}

// ---------------- launch ----------------------------------------------------
extern "C" void kernel_launch(void* const* d_in, const int* in_sizes, int n_in,
                              void* d_out, int out_size)
{
    const float* x         = (const float*)d_in[0];
    const float* mask      = (const float*)d_in[1];
    const float* w_self    = (const float*)d_in[2];
    const float* w_mut     = (const float*)d_in[3];
    const float* w_proj    = (const float*)d_in[4];
    const float* b_proj    = (const float*)d_in[5];
    const float* rpe_table = (const float*)d_in[6];
    const float* pe        = (const float*)d_in[7];
    const int*   rpe_index = (const int*)d_in[8];
    float* out = (float*)d_out;

    unsigned short *xs, *xpes, *cc;
    unsigned short *ws, *wm, *wp;
    float *qs, *qm;
    cudaGetSymbolAddress((void**)&ws, g_ws3);
    cudaGetSymbolAddress((void**)&wm, g_wm3);
    cudaGetSymbolAddress((void**)&wp, g_wp3);
    cudaGetSymbolAddress((void**)&xs, g_xs3);
    cudaGetSymbolAddress((void**)&xpes, g_xpes3);
    cudaGetSymbolAddress((void**)&qs, g_qkv_self);
    cudaGetSymbolAddress((void**)&qm, g_qkv_mut);
    cudaGetSymbolAddress((void**)&cc, g_concat3);

    const int SMEM = 4 * STAGE_ELEMS * (int)sizeof(__nv_bfloat16);   // 73728 B
    cudaFuncSetAttribute(gemm_bf16<384, 384, false>,
                         cudaFuncAttributeMaxDynamicSharedMemorySize, SMEM);
    cudaFuncSetAttribute(gemm_bf16<768, 128, true>,
                         cudaFuncAttributeMaxDynamicSharedMemorySize, SMEM);

    // prep (3 launches -> launch #4 = QKV-self GEMM gets the ncu capture)
    wsplit_all<<<512, 256>>>(w_self, w_mut, w_proj);
    xprep<<<MROWS * 128 / 8 / 256, 256>>>(x, pe);
    prep_misc<<<dim3(4, 4, 513), dim3(32, 8)>>>(mask, rpe_index, rpe_table);

    // QKV GEMMs (K' = 384)
    gemm_bf16<384, 384, false><<<dim3(3, 1024), 256, SMEM>>>(
        (const __nv_bfloat16*)xs,   (const __nv_bfloat16*)ws, nullptr, qs);
    gemm_bf16<384, 384, false><<<dim3(3, 1024), 256, SMEM>>>(
        (const __nv_bfloat16*)xpes, (const __nv_bfloat16*)wm, nullptr, qm);

    // attention
    attn_self<<<dim3(WB, NHEADS), 64>>>();
    attn_mut <<<dim3(WB, NHEADS), 64>>>();

    // projection (K' = 768)
    gemm_bf16<768, 128, true><<<dim3(1, 1024), 256, SMEM>>>(
        (const __nv_bfloat16*)cc, (const __nv_bfloat16*)wp, b_proj, out);
}

// round 7
// speedup vs baseline: 1.0300x; 1.0300x over previous
#include <cuda_runtime.h>
#include <cuda_bf16.h>
#include <cstddef>
#include <cstdint>

#define WB     1024
#define NTOK   128
#define NHEADS 8
#define HD     16
#define MROWS  (WB * NTOK)          // 131072

typedef unsigned long long ull;

// ---------------- scratch (device globals; no runtime allocation) ----------
__device__ unsigned short g_xs3  [(size_t)MROWS * 384];   // x,   K'=384
__device__ unsigned short g_xpes3[(size_t)MROWS * 384];   // x+pe K'=384
__device__ unsigned short g_ws3  [384 * 384];             // w_self
__device__ unsigned short g_wm3  [384 * 384];             // w_mut
__device__ unsigned short g_wp3  [128 * 768];             // w_proj K'=768
__device__ float g_qkv_self[(size_t)MROWS * 384];
__device__ float g_qkv_mut [(size_t)MROWS * 384];
__device__ unsigned short g_concat3[(size_t)MROWS * 768]; // [row][col*3]
__device__ float g_biasT[NHEADS * NTOK * NTOK];           // [h][m][i]
__device__ float g_maskT[512 * NTOK * NTOK];              // [w][m][i]

__device__ __forceinline__ void split_hl(float v, unsigned short& h, unsigned short& l) {
    __nv_bfloat16 hh = __float2bfloat16(v);
    float r = v - __bfloat162float(hh);
    __nv_bfloat16 ll = __float2bfloat16(r);
    h = *(unsigned short*)&hh;
    l = *(unsigned short*)&ll;
}

// ---------------- f32x2 packed math ----------------------------------------
#define FMA2(d, a, b) asm("fma.rn.f32x2 %0, %1, %2, %0;" : "+l"(d) : "l"(a), "l"(b))
#define ADD2(d, a, b) asm("add.rn.f32x2 %0, %1, %2;" : "=l"(d) : "l"(a), "l"(b))
#define MUL2(d, a, b) asm("mul.rn.f32x2 %0, %1, %2;" : "=l"(d) : "l"(a), "l"(b))
#define PACKF2(d, lo, hi) asm("mov.b64 %0, {%1, %2};" : "=l"(d) : "f"(lo), "f"(hi))
#define UNPACKF2(lo, hi, s) asm("mov.b64 {%0, %1}, %2;" : "=f"(lo), "=f"(hi) : "l"(s))

// ---------------- fused prep (ONE launch) -----------------------------------
// blocks [0,512):        weight split (B-side h,l,h)
// blocks [512,8704):     x split (A-side h,h,l) + x+pe split
// blocks [8704,16896):   mask transpose
// blocks [16896,16912):  bias gather
__global__ void __launch_bounds__(256) prep_all(
    const float* __restrict__ x, const float* __restrict__ pe,
    const float* __restrict__ ws, const float* __restrict__ wm,
    const float* __restrict__ wp, const float* __restrict__ mask,
    const int* __restrict__ rpe_index, const float* __restrict__ rpe_table)
{
    const int bid = blockIdx.x, tid = threadIdx.x;
    if (bid < 512) {
        int i = bid * 256 + tid;
        float v; unsigned short* dst;
        if (i < 49152)       { v = ws[i];          dst = g_ws3 + 3 * i; }
        else if (i < 98304)  { v = wm[i - 49152];  dst = g_wm3 + 3 * (i - 49152); }
        else                 { v = wp[i - 98304];  dst = g_wp3 + 3 * (i - 98304); }
        unsigned short h, l;
        split_hl(v, h, l);
        dst[0] = h; dst[1] = l; dst[2] = h;
        return;
    }
    if (bid < 8704) {
        size_t idx8 = (size_t)(bid - 512) * 256 + tid;
        size_t e0 = idx8 * 8;
        int c = (int)(e0 & 127);
        int t = (int)((e0 >> 7) & 127);
        float4 xv0 = ((const float4*)x)[idx8 * 2];
        float4 xv1 = ((const float4*)x)[idx8 * 2 + 1];
        const float* pp = pe + (t & 63) * 128 + c;
        float xe[8] = {xv0.x, xv0.y, xv0.z, xv0.w, xv1.x, xv1.y, xv1.z, xv1.w};
        unsigned short b0[24], b1[24];
#pragma unroll
        for (int j = 0; j < 8; ++j) {
            unsigned short h, l;
            split_hl(xe[j], h, l);
            b0[3 * j] = h; b0[3 * j + 1] = h; b0[3 * j + 2] = l;
            split_hl(xe[j] + pp[j], h, l);
            b1[3 * j] = h; b1[3 * j + 1] = h; b1[3 * j + 2] = l;
        }
        uint4* d0 = (uint4*)(g_xs3 + 3 * e0);
        uint4* d1 = (uint4*)(g_xpes3 + 3 * e0);
        const uint4* s0 = (const uint4*)b0;
        const uint4* s1 = (const uint4*)b1;
        d0[0] = s0[0]; d0[1] = s0[1]; d0[2] = s0[2];
        d1[0] = s1[0]; d1[1] = s1[1]; d1[2] = s1[2];
        return;
    }
    if (bid < 16896) {
        __shared__ float tile[32][33];
        int blin = bid - 8704;
        int w = blin >> 4, quad = blin & 15;
        int x0 = (quad & 3) * 32, y0 = (quad >> 2) * 32;
        int tx = tid & 31, ty = tid >> 5;
        const float* src = mask + (size_t)w * 16384;
        float* dst = g_maskT + (size_t)w * 16384;
#pragma unroll
        for (int j = 0; j < 32; j += 8)
            tile[ty + j][tx] = src[(y0 + ty + j) * 128 + x0 + tx];
        __syncthreads();
#pragma unroll
        for (int j = 0; j < 32; j += 8)
            dst[(x0 + ty + j) * 128 + y0 + tx] = tile[tx][ty + j];
        return;
    }
    {
        int tid0 = (bid - 16896) * 256 + tid;       // 0..4095
#pragma unroll
        for (int j = 0; j < 4; ++j) {
            int t2 = tid0 + j * 4096;               // t2 = m*128 + i
            int i = t2 & 127, m = t2 >> 7;
            int t = rpe_index[i * 128 + m];
#pragma unroll
            for (int h = 0; h < NHEADS; ++h)
                g_biasT[h * 16384 + t2] = rpe_table[t * NHEADS + h];
        }
    }
}

// ---------------- bf16-split tensor-core GEMM (3-stage pipeline) -----------
#define MMA_BF16(d, a, b0r, b1r) \
    asm volatile("mma.sync.aligned.m16n8k16.row.col.f32.bf16.bf16.f32 " \
        "{%0,%1,%2,%3},{%4,%5,%6,%7},{%8,%9},{%0,%1,%2,%3};" \
        : "+f"(d[0]), "+f"(d[1]), "+f"(d[2]), "+f"(d[3]) \
        : "r"(a[0]), "r"(a[1]), "r"(a[2]), "r"(a[3]), "r"(b0r), "r"(b1r))

#define LDSM4(r0, r1, r2, r3, addr) \
    asm volatile("ldmatrix.sync.aligned.m8n8.x4.shared.b16 {%0,%1,%2,%3}, [%4];" \
        : "=r"(r0), "=r"(r1), "=r"(r2), "=r"(r3) : "r"(addr))

#define CP16(dst, src) \
    asm volatile("cp.async.cg.shared.global [%0], [%1], 16;" :: "r"(dst), "l"(src))

#define PITCH 72
#define STAGE_ELEMS (128 * PITCH)
#define NSTAGE 3

template<int KTOT, int NTOT, bool BIAS>
__global__ void __launch_bounds__(256) gemm_bf16(
    const __nv_bfloat16* __restrict__ A, const __nv_bfloat16* __restrict__ W,
    const float* __restrict__ bvec, float* __restrict__ C)
{
    extern __shared__ __nv_bfloat16 smem[];
    __nv_bfloat16* As = smem;                           // [3][128*72]
    __nv_bfloat16* Bs = smem + NSTAGE * STAGE_ELEMS;    // [3][128*72]

    const int tid = threadIdx.x;
    const int lane = tid & 31, wid = tid >> 5;
    const int wm = (wid & 1) * 64, wn = (wid >> 1) * 32;
    const int g = lane >> 2, tg = lane & 3;
    const size_t row0 = (size_t)blockIdx.y * 128;
    const int col0 = blockIdx.x * 128;
    constexpr int NC = KTOT / 64;

    const int ldr = tid >> 1;
    const int ldu = (tid & 1) * 4;

    float acc[4][4][4] = {};

    const int a_row = wm + (lane & 15);
    const int a_col = (lane >> 4) * 8;
    const int bq = lane >> 3;
    const int b_row = wn + ((bq >> 1) * 8) + (lane & 7);
    const int b_col = (bq & 1) * 8;

#define LOAD_STAGE(kc, s)                                                        \
    {                                                                            \
        const __nv_bfloat16* Ab = A + (row0 + ldr) * KTOT + (kc) * 64;           \
        const __nv_bfloat16* Wb = W + (size_t)(col0 + ldr) * KTOT + (kc) * 64;   \
        __nv_bfloat16* Ad = As + (s) * STAGE_ELEMS + ldr * PITCH;                \
        __nv_bfloat16* Bd = Bs + (s) * STAGE_ELEMS + ldr * PITCH;                \
        _Pragma("unroll")                                                        \
        for (int u = 0; u < 4; ++u) {                                            \
            unsigned da = (unsigned)__cvta_generic_to_shared(Ad + (ldu + u) * 8);\
            CP16(da, Ab + (ldu + u) * 8);                                        \
            unsigned db = (unsigned)__cvta_generic_to_shared(Bd + (ldu + u) * 8);\
            CP16(db, Wb + (ldu + u) * 8);                                        \
        }                                                                        \
        asm volatile("cp.async.commit_group;");                                  \
    }

    LOAD_STAGE(0, 0);
    LOAD_STAGE(1, 1);

#pragma unroll
    for (int kc = 0; kc < NC; ++kc) {
        const int cur = kc % NSTAGE;
        if (kc + 2 < NC) {
            asm volatile("cp.async.wait_group 1;");
        } else {
            asm volatile("cp.async.wait_group 0;");
        }
        __syncthreads();
        if (kc + 2 < NC) LOAD_STAGE(kc + 2, (kc + 2) % NSTAGE);

        const __nv_bfloat16* Ad = As + cur * STAGE_ELEMS;
        const __nv_bfloat16* Bd = Bs + cur * STAGE_ELEMS;
#pragma unroll
        for (int ks = 0; ks < 4; ++ks) {
            const int kb = ks * 16;
            uint32_t a[4][4], b[2][4];
#pragma unroll
            for (int mt = 0; mt < 4; ++mt) {
                unsigned ad = (unsigned)__cvta_generic_to_shared(
                    Ad + (a_row + mt * 16) * PITCH + kb + a_col);
                LDSM4(a[mt][0], a[mt][1], a[mt][2], a[mt][3], ad);
            }
#pragma unroll
            for (int p = 0; p < 2; ++p) {
                unsigned bd = (unsigned)__cvta_generic_to_shared(
                    Bd + (b_row + p * 16) * PITCH + kb + b_col);
                LDSM4(b[p][0], b[p][1], b[p][2], b[p][3], bd);
            }
#pragma unroll
            for (int mt = 0; mt < 4; ++mt)
#pragma unroll
                for (int nt = 0; nt < 4; ++nt)
                    MMA_BF16(acc[mt][nt], a[mt], b[nt >> 1][(nt & 1) * 2],
                             b[nt >> 1][(nt & 1) * 2 + 1]);
        }
        __syncthreads();
    }

#pragma unroll
    for (int mt = 0; mt < 4; ++mt) {
#pragma unroll
        for (int nt = 0; nt < 4; ++nt) {
            size_t row = row0 + wm + mt * 16 + g;
            int col = col0 + wn + nt * 8 + 2 * tg;
            float b0 = BIAS ? bvec[col] : 0.f, b1 = BIAS ? bvec[col + 1] : 0.f;
            *(float2*)&C[row * NTOT + col] =
                make_float2(acc[mt][nt][0] + b0, acc[mt][nt][1] + b1);
            *(float2*)&C[(row + 8) * NTOT + col] =
                make_float2(acc[mt][nt][2] + b0, acc[mt][nt][3] + b1);
        }
    }
}

// ---------------- write attention output as A-side triplets -----------------
__device__ __forceinline__ void store_triplets16(unsigned short* dst, const float* v)
{
    unsigned short ob[48];
#pragma unroll
    for (int c = 0; c < 16; ++c) {
        unsigned short h, l;
        split_hl(v[c], h, l);
        ob[3 * c] = h; ob[3 * c + 1] = h; ob[3 * c + 2] = l;
    }
    uint4* d = (uint4*)dst;
    const uint4* s = (const uint4*)ob;
#pragma unroll
    for (int j = 0; j < 6; ++j) d[j] = s[j];
}

// ---------------- merged attention (self: y<8, mutual: y>=8) ----------------
__global__ void __launch_bounds__(64) attn_all()
{
    const int b = blockIdx.x, t = threadIdx.x;
    __shared__ ulonglong2 ks[NTOK * 4];
    __shared__ ulonglong2 vs[NTOK * 4];
    const ull C025 = 0x3E8000003E800000ull;          // (0.25f, 0.25f)

    if (blockIdx.y < 8) {
        const int h = blockIdx.y;
        const float* base = g_qkv_self + (size_t)b * NTOK * 384;
#pragma unroll
        for (int rr = 0; rr < 2; ++rr) {
            int r = t + rr * 64;
            const ulonglong2* kr = (const ulonglong2*)(base + r * 384 + 128 + h * HD);
            const ulonglong2* vr = (const ulonglong2*)(base + r * 384 + 256 + h * HD);
#pragma unroll
            for (int j = 0; j < 4; ++j) { ks[r * 4 + j] = kr[j]; vs[r * 4 + j] = vr[j]; }
        }
        ull qa[8], qb[8];
        {
            const ull* q0 = (const ull*)(base + t * 384 + h * HD);
            const ull* q1 = (const ull*)(base + (t + 64) * 384 + h * HD);
#pragma unroll
            for (int j = 0; j < 8; ++j) { MUL2(qa[j], q0[j], C025); MUL2(qb[j], q1[j], C025); }
        }
        __syncthreads();

        const float* ma = g_maskT + (size_t)(b & 511) * 16384 + t;
        const float* mb = ma + 64;
        const float* ba = g_biasT + h * 16384 + t;
        const float* bb = ba + 64;

        ull acca[8] = {}, accb[8] = {};
        float sma = 0.f, smb = 0.f;
#pragma unroll 2
        for (int m = 0; m < NTOK; ++m) {
            ulonglong2 k0 = ks[m * 4 + 0], k1 = ks[m * 4 + 1];
            ulonglong2 k2 = ks[m * 4 + 2], k3 = ks[m * 4 + 3];
            ull da0 = 0, da1 = 0, db0 = 0, db1 = 0;
            FMA2(da0, qa[0], k0.x); FMA2(da1, qa[1], k0.y);
            FMA2(da0, qa[2], k1.x); FMA2(da1, qa[3], k1.y);
            FMA2(da0, qa[4], k2.x); FMA2(da1, qa[5], k2.y);
            FMA2(da0, qa[6], k3.x); FMA2(da1, qa[7], k3.y);
            FMA2(db0, qb[0], k0.x); FMA2(db1, qb[1], k0.y);
            FMA2(db0, qb[2], k1.x); FMA2(db1, qb[3], k1.y);
            FMA2(db0, qb[4], k2.x); FMA2(db1, qb[5], k2.y);
            FMA2(db0, qb[6], k3.x); FMA2(db1, qb[7], k3.y);
            ull ds; float lo, hi;
            ADD2(ds, da0, da1); UNPACKF2(lo, hi, ds);
            float sa = lo + hi + ma[m * 128] + ba[m * 128];
            ADD2(ds, db0, db1); UNPACKF2(lo, hi, ds);
            float sb = lo + hi + mb[m * 128] + bb[m * 128];
            float pa = __expf(sa), pb = __expf(sb);
            sma += pa; smb += pb;
            ull pa2, pb2; PACKF2(pa2, pa, pa); PACKF2(pb2, pb, pb);
            ulonglong2 v0 = vs[m * 4 + 0], v1 = vs[m * 4 + 1];
            ulonglong2 v2 = vs[m * 4 + 2], v3 = vs[m * 4 + 3];
            FMA2(acca[0], pa2, v0.x); FMA2(acca[1], pa2, v0.y);
            FMA2(acca[2], pa2, v1.x); FMA2(acca[3], pa2, v1.y);
            FMA2(acca[4], pa2, v2.x); FMA2(acca[5], pa2, v2.y);
            FMA2(acca[6], pa2, v3.x); FMA2(acca[7], pa2, v3.y);
            FMA2(accb[0], pb2, v0.x); FMA2(accb[1], pb2, v0.y);
            FMA2(accb[2], pb2, v1.x); FMA2(accb[3], pb2, v1.y);
            FMA2(accb[4], pb2, v2.x); FMA2(accb[5], pb2, v2.y);
            FMA2(accb[6], pb2, v3.x); FMA2(accb[7], pb2, v3.y);
        }
        float ia = 1.f / sma, ib = 1.f / smb;
        float oa[16], ob[16];
#pragma unroll
        for (int j = 0; j < 8; ++j) {
            float lo, hi;
            UNPACKF2(lo, hi, acca[j]); oa[2 * j] = lo * ia; oa[2 * j + 1] = hi * ia;
            UNPACKF2(lo, hi, accb[j]); ob[2 * j] = lo * ib; ob[2 * j + 1] = hi * ib;
        }
        store_triplets16(g_concat3 + ((size_t)b * NTOK + t) * 768 + (128 + h * HD) * 3, oa);
        store_triplets16(g_concat3 + ((size_t)b * NTOK + t + 64) * 768 + (128 + h * HD) * 3, ob);
    } else {
        const int h = blockIdx.y - 8;
        const float* base = g_qkv_mut + (size_t)b * NTOK * 384;
#pragma unroll
        for (int rr = 0; rr < 2; ++rr) {
            int r = t + rr * 64;
            const ulonglong2* kr = (const ulonglong2*)(base + r * 384 + 128 + h * HD);
            const ulonglong2* vr = (const ulonglong2*)(base + r * 384 + 256 + h * HD);
#pragma unroll
            for (int j = 0; j < 4; ++j) { ks[r * 4 + j] = kr[j]; vs[r * 4 + j] = vr[j]; }
        }
        ull qa[8], qb[8];
        {
            const ull* q0 = (const ull*)(base + (64 + t) * 384 + h * HD);
            const ull* q1 = (const ull*)(base + t * 384 + h * HD);
#pragma unroll
            for (int j = 0; j < 8; ++j) { MUL2(qa[j], q0[j], C025); MUL2(qb[j], q1[j], C025); }
        }
        __syncthreads();

        const float* mk = g_maskT + (size_t)(b & 511) * 16384 + t;

        ull acca[8] = {}, accb[8] = {};
        float sma = 0.f, smb = 0.f;
#pragma unroll 2
        for (int m = 0; m < 64; ++m) {
            ulonglong2 ka0 = ks[m * 4 + 0], ka1 = ks[m * 4 + 1];
            ulonglong2 ka2 = ks[m * 4 + 2], ka3 = ks[m * 4 + 3];
            ulonglong2 kb0 = ks[(64 + m) * 4 + 0], kb1 = ks[(64 + m) * 4 + 1];
            ulonglong2 kb2 = ks[(64 + m) * 4 + 2], kb3 = ks[(64 + m) * 4 + 3];
            ull da0 = 0, da1 = 0, db0 = 0, db1 = 0;
            FMA2(da0, qa[0], ka0.x); FMA2(da1, qa[1], ka0.y);
            FMA2(da0, qa[2], ka1.x); FMA2(da1, qa[3], ka1.y);
            FMA2(da0, qa[4], ka2.x); FMA2(da1, qa[5], ka2.y);
            FMA2(da0, qa[6], ka3.x); FMA2(da1, qa[7], ka3.y);
            FMA2(db0, qb[0], kb0.x); FMA2(db1, qb[1], kb0.y);
            FMA2(db0, qb[2], kb1.x); FMA2(db1, qb[3], kb1.y);
            FMA2(db0, qb[4], kb2.x); FMA2(db1, qb[5], kb2.y);
            FMA2(db0, qb[6], kb3.x); FMA2(db1, qb[7], kb3.y);
            float mv = mk[m * 128];
            ull ds; float lo, hi;
            ADD2(ds, da0, da1); UNPACKF2(lo, hi, ds);
            float sa = lo + hi + mv;
            ADD2(ds, db0, db1); UNPACKF2(lo, hi, ds);
            float sb = lo + hi + mv;
            float pa = __expf(sa), pb = __expf(sb);
            sma += pa; smb += pb;
            ull pa2, pb2; PACKF2(pa2, pa, pa); PACKF2(pb2, pb, pb);
            ulonglong2 va0 = vs[m * 4 + 0], va1 = vs[m * 4 + 1];
            ulonglong2 va2 = vs[m * 4 + 2], va3 = vs[m * 4 + 3];
            ulonglong2 vb0 = vs[(64 + m) * 4 + 0], vb1 = vs[(64 + m) * 4 + 1];
            ulonglong2 vb2 = vs[(64 + m) * 4 + 2], vb3 = vs[(64 + m) * 4 + 3];
            FMA2(acca[0], pa2, va0.x); FMA2(acca[1], pa2, va0.y);
            FMA2(acca[2], pa2, va1.x); FMA2(acca[3], pa2, va1.y);
            FMA2(acca[4], pa2, va2.x); FMA2(acca[5], pa2, va2.y);
            FMA2(acca[6], pa2, va3.x); FMA2(acca[7], pa2, va3.y);
            FMA2(accb[0], pb2, vb0.x); FMA2(accb[1], pb2, vb0.y);
            FMA2(accb[2], pb2, vb1.x); FMA2(accb[3], pb2, vb1.y);
            FMA2(accb[4], pb2, vb2.x); FMA2(accb[5], pb2, vb2.y);
            FMA2(accb[6], pb2, vb3.x); FMA2(accb[7], pb2, vb3.y);
        }
        float ia = 1.f / sma, ib = 1.f / smb;
        float oa[16], ob[16];
#pragma unroll
        for (int j = 0; j < 8; ++j) {
            float lo, hi;
            UNPACKF2(lo, hi, acca[j]); oa[2 * j] = lo * ia; oa[2 * j + 1] = hi * ia;
            UNPACKF2(lo, hi, accb[j]); ob[2 * j] = lo * ib; ob[2 * j + 1] = hi * ib;
        }
        store_triplets16(g_concat3 + ((size_t)b * NTOK + t) * 768 + (h * HD) * 3, oa);
        store_triplets16(g_concat3 + ((size_t)b * NTOK + t + 64) * 768 + (h * HD) * 3, ob);
    }
}

// ---------------- launch ----------------------------------------------------
extern "C" void kernel_launch(void* const* d_in, const int* in_sizes, int n_in,
                              void* d_out, int out_size)
{
    const float* x         = (const float*)d_in[0];
    const float* mask      = (const float*)d_in[1];
    const float* w_self    = (const float*)d_in[2];
    const float* w_mut     = (const float*)d_in[3];
    const float* w_proj    = (const float*)d_in[4];
    const float* b_proj    = (const float*)d_in[5];
    const float* rpe_table = (const float*)d_in[6];
    const float* pe        = (const float*)d_in[7];
    const int*   rpe_index = (const int*)d_in[8];
    float* out = (float*)d_out;

    unsigned short *xs, *xpes, *cc, *ws, *wm, *wp;
    float *qs, *qm;
    cudaGetSymbolAddress((void**)&ws, g_ws3);
    cudaGetSymbolAddress((void**)&wm, g_wm3);
    cudaGetSymbolAddress((void**)&wp, g_wp3);
    cudaGetSymbolAddress((void**)&xs, g_xs3);
    cudaGetSymbolAddress((void**)&xpes, g_xpes3);
    cudaGetSymbolAddress((void**)&qs, g_qkv_self);
    cudaGetSymbolAddress((void**)&qm, g_qkv_mut);
    cudaGetSymbolAddress((void**)&cc, g_concat3);

    const int SMEM = 2 * NSTAGE * STAGE_ELEMS * (int)sizeof(__nv_bfloat16); // 110592
    cudaFuncSetAttribute(gemm_bf16<384, 384, false>,
                         cudaFuncAttributeMaxDynamicSharedMemorySize, SMEM);
    cudaFuncSetAttribute(gemm_bf16<768, 128, true>,
                         cudaFuncAttributeMaxDynamicSharedMemorySize, SMEM);

    // launch 1: all prep
    prep_all<<<16912, 256>>>(x, pe, w_self, w_mut, w_proj, mask, rpe_index, rpe_table);

    // launches 2,3: QKV GEMMs (K' = 384)
    gemm_bf16<384, 384, false><<<dim3(3, 1024), 256, SMEM>>>(
        (const __nv_bfloat16*)xs,   (const __nv_bfloat16*)ws, nullptr, qs);
    gemm_bf16<384, 384, false><<<dim3(3, 1024), 256, SMEM>>>(
        (const __nv_bfloat16*)xpes, (const __nv_bfloat16*)wm, nullptr, qm);

    // launch 4: merged attention  (<- ncu capture slot)
    attn_all<<<dim3(WB, 16), 64>>>();

    // launch 5: projection (K' = 768)
    gemm_bf16<768, 128, true><<<dim3(1, 1024), 256, SMEM>>>(
        (const __nv_bfloat16*)cc, (const __nv_bfloat16*)wp, b_proj, out);
}

// round 9
// speedup vs baseline: 1.1805x; 1.1461x over previous
#include <cuda_runtime.h>
#include <cuda_bf16.h>
#include <cstddef>
#include <cstdint>

#define WB     1024
#define NTOK   128
#define NHEADS 8
#define HD     16
#define MROWS  (WB * NTOK)          // 131072

typedef unsigned long long ull;

// ---------------- scratch (device globals; no runtime allocation) ----------
__device__ unsigned short g_xs3  [(size_t)MROWS * 384];
__device__ unsigned short g_xpes3[(size_t)MROWS * 384];
__device__ unsigned short g_ws3  [384 * 384];
__device__ unsigned short g_wm3  [384 * 384];
__device__ unsigned short g_wp3  [128 * 768];
__device__ float g_qkv_self[(size_t)MROWS * 384];
__device__ float g_qkv_mut [(size_t)MROWS * 384];
__device__ unsigned short g_concat3[(size_t)MROWS * 768];
__device__ float g_maskT[512 * NTOK * NTOK];                  // [w][m][i]
__device__ float g_mbias[(size_t)NHEADS * 512 * NTOK * NTOK]; // [h][w][m][i]

__device__ __forceinline__ void split_hl(float v, unsigned short& h, unsigned short& l) {
    __nv_bfloat16 hh = __float2bfloat16(v);
    float r = v - __bfloat162float(hh);
    __nv_bfloat16 ll = __float2bfloat16(r);
    h = *(unsigned short*)&hh;
    l = *(unsigned short*)&ll;
}

// ---------------- f32x2 packed math ----------------------------------------
#define FMA2(d, a, b) asm("fma.rn.f32x2 %0, %1, %2, %0;" : "+l"(d) : "l"(a), "l"(b))
#define ADD2(d, a, b) asm("add.rn.f32x2 %0, %1, %2;" : "=l"(d) : "l"(a), "l"(b))
#define MUL2(d, a, b) asm("mul.rn.f32x2 %0, %1, %2;" : "=l"(d) : "l"(a), "l"(b))
#define PACKF2(d, lo, hi) asm("mov.b64 %0, {%1, %2};" : "=l"(d) : "f"(lo), "f"(hi))
#define UNPACKF2(lo, hi, s) asm("mov.b64 {%0, %1}, %2;" : "=f"(lo), "=f"(hi) : "l"(s))

// ---------------- fused prep (ONE launch) -----------------------------------
// blocks [0,512):      weight split (B-side h,l,h)
// blocks [512,8704):   x split (A-side h,h,l) + x+pe split
// blocks [8704,16896): mask transpose -> maskT  AND  mbias = maskT + rpe bias
__global__ void __launch_bounds__(256) prep_all(
    const float* __restrict__ x, const float* __restrict__ pe,
    const float* __restrict__ ws, const float* __restrict__ wm,
    const float* __restrict__ wp, const float* __restrict__ mask,
    const int* __restrict__ rpe_index, const float* __restrict__ rpe_table)
{
    const int bid = blockIdx.x, tid = threadIdx.x;
    if (bid < 512) {
        int i = bid * 256 + tid;
        float v; unsigned short* dst;
        if (i < 49152)       { v = ws[i];          dst = g_ws3 + 3 * i; }
        else if (i < 98304)  { v = wm[i - 49152];  dst = g_wm3 + 3 * (i - 49152); }
        else                 { v = wp[i - 98304];  dst = g_wp3 + 3 * (i - 98304); }
        unsigned short h, l;
        split_hl(v, h, l);
        dst[0] = h; dst[1] = l; dst[2] = h;
        return;
    }
    if (bid < 8704) {
        size_t idx8 = (size_t)(bid - 512) * 256 + tid;
        size_t e0 = idx8 * 8;
        int c = (int)(e0 & 127);
        int t = (int)((e0 >> 7) & 127);
        float4 xv0 = ((const float4*)x)[idx8 * 2];
        float4 xv1 = ((const float4*)x)[idx8 * 2 + 1];
        const float* pp = pe + (t & 63) * 128 + c;
        float xe[8] = {xv0.x, xv0.y, xv0.z, xv0.w, xv1.x, xv1.y, xv1.z, xv1.w};
        unsigned short b0[24], b1[24];
#pragma unroll
        for (int j = 0; j < 8; ++j) {
            unsigned short h, l;
            split_hl(xe[j], h, l);
            b0[3 * j] = h; b0[3 * j + 1] = h; b0[3 * j + 2] = l;
            split_hl(xe[j] + pp[j], h, l);
            b1[3 * j] = h; b1[3 * j + 1] = h; b1[3 * j + 2] = l;
        }
        uint4* d0 = (uint4*)(g_xs3 + 3 * e0);
        uint4* d1 = (uint4*)(g_xpes3 + 3 * e0);
        const uint4* s0 = (const uint4*)b0;
        const uint4* s1 = (const uint4*)b1;
        d0[0] = s0[0]; d0[1] = s0[1]; d0[2] = s0[2];
        d1[0] = s1[0]; d1[1] = s1[1]; d1[2] = s1[2];
        return;
    }
    {
        __shared__ float tile[32][33];
        __shared__ int   itile[32][33];
        int blin = bid - 8704;
        int w = blin >> 4, quad = blin & 15;
        int x0 = (quad & 3) * 32, y0 = (quad >> 2) * 32;   // x0: m dir, y0: i dir
        int tx = tid & 31, ty = tid >> 5;                  // 32 x 8
        const float* src = mask + (size_t)w * 16384;
        float* dstT = g_maskT + (size_t)w * 16384;
#pragma unroll
        for (int j = 0; j < 32; j += 8) {
            tile[ty + j][tx]  = src[(y0 + ty + j) * 128 + x0 + tx];          // mask[w][i][m]
            itile[ty + j][tx] = rpe_index[(y0 + ty + j) * 128 + x0 + tx];    // idx[i][m]
        }
        __syncthreads();
#pragma unroll
        for (int j = 0; j < 32; j += 8) {
            int m = x0 + ty + j, i = y0 + tx;
            float mval = tile[tx][ty + j];                 // mask[w][i][m]
            dstT[m * 128 + i] = mval;
            int tix = itile[tx][ty + j];
            float4 r0 = *(const float4*)(rpe_table + tix * 8);
            float4 r1 = *(const float4*)(rpe_table + tix * 8 + 4);
            float rv[8] = {r0.x, r0.y, r0.z, r0.w, r1.x, r1.y, r1.z, r1.w};
            size_t o = (size_t)w * 16384 + m * 128 + i;
#pragma unroll
            for (int h = 0; h < NHEADS; ++h)
                g_mbias[(size_t)h * 512 * 16384 + o] = mval + rv[h];
        }
        return;
    }
}

// ---------------- bf16-split tensor-core GEMM (3-stage pipeline) -----------
#define MMA_BF16(d, a, b0r, b1r) \
    asm volatile("mma.sync.aligned.m16n8k16.row.col.f32.bf16.bf16.f32 " \
        "{%0,%1,%2,%3},{%4,%5,%6,%7},{%8,%9},{%0,%1,%2,%3};" \
        : "+f"(d[0]), "+f"(d[1]), "+f"(d[2]), "+f"(d[3]) \
        : "r"(a[0]), "r"(a[1]), "r"(a[2]), "r"(a[3]), "r"(b0r), "r"(b1r))

#define LDSM4(r0, r1, r2, r3, addr) \
    asm volatile("ldmatrix.sync.aligned.m8n8.x4.shared.b16 {%0,%1,%2,%3}, [%4];" \
        : "=r"(r0), "=r"(r1), "=r"(r2), "=r"(r3) : "r"(addr))

#define CP16(dst, src) \
    asm volatile("cp.async.cg.shared.global [%0], [%1], 16;" :: "r"(dst), "l"(src))

#define PITCH 72
#define STAGE_ELEMS (128 * PITCH)
#define NSTAGE 3

template<int KTOT, int NTOT, bool BIAS>
__global__ void __launch_bounds__(256) gemm_bf16(
    const __nv_bfloat16* __restrict__ A, const __nv_bfloat16* __restrict__ W,
    const float* __restrict__ bvec, float* __restrict__ C)
{
    extern __shared__ __nv_bfloat16 smem[];
    __nv_bfloat16* As = smem;
    __nv_bfloat16* Bs = smem + NSTAGE * STAGE_ELEMS;

    const int tid = threadIdx.x;
    const int lane = tid & 31, wid = tid >> 5;
    const int wm = (wid & 1) * 64, wn = (wid >> 1) * 32;
    const int g = lane >> 2, tg = lane & 3;
    const size_t row0 = (size_t)blockIdx.y * 128;
    const int col0 = blockIdx.x * 128;
    constexpr int NC = KTOT / 64;

    const int ldr = tid >> 1;
    const int ldu = (tid & 1) * 4;

    float acc[4][4][4] = {};

    const int a_row = wm + (lane & 15);
    const int a_col = (lane >> 4) * 8;
    const int bq = lane >> 3;
    const int b_row = wn + ((bq >> 1) * 8) + (lane & 7);
    const int b_col = (bq & 1) * 8;

#define LOAD_STAGE(kc, s)                                                        \
    {                                                                            \
        const __nv_bfloat16* Ab = A + (row0 + ldr) * KTOT + (kc) * 64;           \
        const __nv_bfloat16* Wb = W + (size_t)(col0 + ldr) * KTOT + (kc) * 64;   \
        __nv_bfloat16* Ad = As + (s) * STAGE_ELEMS + ldr * PITCH;                \
        __nv_bfloat16* Bd = Bs + (s) * STAGE_ELEMS + ldr * PITCH;                \
        _Pragma("unroll")                                                        \
        for (int u = 0; u < 4; ++u) {                                            \
            unsigned da = (unsigned)__cvta_generic_to_shared(Ad + (ldu + u) * 8);\
            CP16(da, Ab + (ldu + u) * 8);                                        \
            unsigned db = (unsigned)__cvta_generic_to_shared(Bd + (ldu + u) * 8);\
            CP16(db, Wb + (ldu + u) * 8);                                        \
        }                                                                        \
        asm volatile("cp.async.commit_group;");                                  \
    }

    LOAD_STAGE(0, 0);
    LOAD_STAGE(1, 1);

#pragma unroll
    for (int kc = 0; kc < NC; ++kc) {
        const int cur = kc % NSTAGE;
        if (kc + 2 < NC) {
            asm volatile("cp.async.wait_group 1;");
        } else {
            asm volatile("cp.async.wait_group 0;");
        }
        __syncthreads();
        if (kc + 2 < NC) LOAD_STAGE(kc + 2, (kc + 2) % NSTAGE);

        const __nv_bfloat16* Ad = As + cur * STAGE_ELEMS;
        const __nv_bfloat16* Bd = Bs + cur * STAGE_ELEMS;
#pragma unroll
        for (int ks = 0; ks < 4; ++ks) {
            const int kb = ks * 16;
            uint32_t a[4][4], b[2][4];
#pragma unroll
            for (int mt = 0; mt < 4; ++mt) {
                unsigned ad = (unsigned)__cvta_generic_to_shared(
                    Ad + (a_row + mt * 16) * PITCH + kb + a_col);
                LDSM4(a[mt][0], a[mt][1], a[mt][2], a[mt][3], ad);
            }
#pragma unroll
            for (int p = 0; p < 2; ++p) {
                unsigned bd = (unsigned)__cvta_generic_to_shared(
                    Bd + (b_row + p * 16) * PITCH + kb + b_col);
                LDSM4(b[p][0], b[p][1], b[p][2], b[p][3], bd);
            }
#pragma unroll
            for (int mt = 0; mt < 4; ++mt)
#pragma unroll
                for (int nt = 0; nt < 4; ++nt)
                    MMA_BF16(acc[mt][nt], a[mt], b[nt >> 1][(nt & 1) * 2],
                             b[nt >> 1][(nt & 1) * 2 + 1]);
        }
        __syncthreads();
    }

#pragma unroll
    for (int mt = 0; mt < 4; ++mt) {
#pragma unroll
        for (int nt = 0; nt < 4; ++nt) {
            size_t row = row0 + wm + mt * 16 + g;
            int col = col0 + wn + nt * 8 + 2 * tg;
            float b0 = BIAS ? bvec[col] : 0.f, b1 = BIAS ? bvec[col + 1] : 0.f;
            *(float2*)&C[row * NTOT + col] =
                make_float2(acc[mt][nt][0] + b0, acc[mt][nt][1] + b1);
            *(float2*)&C[(row + 8) * NTOT + col] =
                make_float2(acc[mt][nt][2] + b0, acc[mt][nt][3] + b1);
        }
    }
}

// ---------------- write attention output as A-side triplets -----------------
__device__ __forceinline__ void store_triplets16(unsigned short* dst, const float* v)
{
    unsigned short ob[48];
#pragma unroll
    for (int c = 0; c < 16; ++c) {
        unsigned short h, l;
        split_hl(v[c], h, l);
        ob[3 * c] = h; ob[3 * c + 1] = h; ob[3 * c + 2] = l;
    }
    uint4* d = (uint4*)dst;
    const uint4* s = (const uint4*)ob;
#pragma unroll
    for (int j = 0; j < 6; ++j) d[j] = s[j];
}

// ---------------- merged attention (self: y<8, mutual: y>=8) ----------------
// chunked register prefetch of mbias / mask (8 m-values ahead)
__global__ void __launch_bounds__(64) attn_all()
{
    const int b = blockIdx.x, t = threadIdx.x;
    __shared__ ulonglong2 ks[NTOK * 4];
    __shared__ ulonglong2 vs[NTOK * 4];
    const ull C025 = 0x3E8000003E800000ull;          // (0.25f, 0.25f)

    if (blockIdx.y < 8) {
        const int h = blockIdx.y;
        const float* base = g_qkv_self + (size_t)b * NTOK * 384;
#pragma unroll
        for (int rr = 0; rr < 2; ++rr) {
            int r = t + rr * 64;
            const ulonglong2* kr = (const ulonglong2*)(base + r * 384 + 128 + h * HD);
            const ulonglong2* vr = (const ulonglong2*)(base + r * 384 + 256 + h * HD);
#pragma unroll
            for (int j = 0; j < 4; ++j) { ks[r * 4 + j] = kr[j]; vs[r * 4 + j] = vr[j]; }
        }
        ull qa[8], qb[8];
        {
            const ull* q0 = (const ull*)(base + t * 384 + h * HD);
            const ull* q1 = (const ull*)(base + (t + 64) * 384 + h * HD);
#pragma unroll
            for (int j = 0; j < 8; ++j) { MUL2(qa[j], q0[j], C025); MUL2(qb[j], q1[j], C025); }
        }
        __syncthreads();

        // fused mask+bias column for queries t and t+64
        const float* ca = g_mbias + ((size_t)h * 512 + (b & 511)) * 16384 + t;

        ull acca[8] = {}, accb[8] = {};
        float sma = 0.f, smb = 0.f;

        float fa[8], fb[8];
#pragma unroll
        for (int j = 0; j < 8; ++j) { fa[j] = ca[j * 128]; fb[j] = ca[j * 128 + 64]; }

        for (int ch = 0; ch < 16; ++ch) {
            float na[8], nb[8];
            if (ch < 15) {
#pragma unroll
                for (int j = 0; j < 8; ++j) {
                    na[j] = ca[(ch * 8 + 8 + j) * 128];
                    nb[j] = ca[(ch * 8 + 8 + j) * 128 + 64];
                }
            }
#pragma unroll
            for (int j = 0; j < 8; ++j) {
                const int m = ch * 8 + j;
                ulonglong2 k0 = ks[m * 4 + 0], k1 = ks[m * 4 + 1];
                ulonglong2 k2 = ks[m * 4 + 2], k3 = ks[m * 4 + 3];
                ull da0 = 0, da1 = 0, db0 = 0, db1 = 0;
                FMA2(da0, qa[0], k0.x); FMA2(da1, qa[1], k0.y);
                FMA2(da0, qa[2], k1.x); FMA2(da1, qa[3], k1.y);
                FMA2(da0, qa[4], k2.x); FMA2(da1, qa[5], k2.y);
                FMA2(da0, qa[6], k3.x); FMA2(da1, qa[7], k3.y);
                FMA2(db0, qb[0], k0.x); FMA2(db1, qb[1], k0.y);
                FMA2(db0, qb[2], k1.x); FMA2(db1, qb[3], k1.y);
                FMA2(db0, qb[4], k2.x); FMA2(db1, qb[5], k2.y);
                FMA2(db0, qb[6], k3.x); FMA2(db1, qb[7], k3.y);
                ull ds; float lo, hi;
                ADD2(ds, da0, da1); UNPACKF2(lo, hi, ds);
                float sa = lo + hi + fa[j];
                ADD2(ds, db0, db1); UNPACKF2(lo, hi, ds);
                float sb = lo + hi + fb[j];
                float pa = __expf(sa), pb = __expf(sb);
                sma += pa; smb += pb;
                ull pa2, pb2; PACKF2(pa2, pa, pa); PACKF2(pb2, pb, pb);
                ulonglong2 v0 = vs[m * 4 + 0], v1 = vs[m * 4 + 1];
                ulonglong2 v2 = vs[m * 4 + 2], v3 = vs[m * 4 + 3];
                FMA2(acca[0], pa2, v0.x); FMA2(acca[1], pa2, v0.y);
                FMA2(acca[2], pa2, v1.x); FMA2(acca[3], pa2, v1.y);
                FMA2(acca[4], pa2, v2.x); FMA2(acca[5], pa2, v2.y);
                FMA2(acca[6], pa2, v3.x); FMA2(acca[7], pa2, v3.y);
                FMA2(accb[0], pb2, v0.x); FMA2(accb[1], pb2, v0.y);
                FMA2(accb[2], pb2, v1.x); FMA2(accb[3], pb2, v1.y);
                FMA2(accb[4], pb2, v2.x); FMA2(accb[5], pb2, v2.y);
                FMA2(accb[6], pb2, v3.x); FMA2(accb[7], pb2, v3.y);
            }
            if (ch < 15) {
#pragma unroll
                for (int j = 0; j < 8; ++j) { fa[j] = na[j]; fb[j] = nb[j]; }
            }
        }
        float ia = 1.f / sma, ib = 1.f / smb;
        float oa[16], ob[16];
#pragma unroll
        for (int j = 0; j < 8; ++j) {
            float lo, hi;
            UNPACKF2(lo, hi, acca[j]); oa[2 * j] = lo * ia; oa[2 * j + 1] = hi * ia;
            UNPACKF2(lo, hi, accb[j]); ob[2 * j] = lo * ib; ob[2 * j + 1] = hi * ib;
        }
        store_triplets16(g_concat3 + ((size_t)b * NTOK + t) * 768 + (128 + h * HD) * 3, oa);
        store_triplets16(g_concat3 + ((size_t)b * NTOK + t + 64) * 768 + (128 + h * HD) * 3, ob);
    } else {
        const int h = blockIdx.y - 8;
        const float* base = g_qkv_mut + (size_t)b * NTOK * 384;
#pragma unroll
        for (int rr = 0; rr < 2; ++rr) {
            int r = t + rr * 64;
            const ulonglong2* kr = (const ulonglong2*)(base + r * 384 + 128 + h * HD);
            const ulonglong2* vr = (const ulonglong2*)(base + r * 384 + 256 + h * HD);
#pragma unroll
            for (int j = 0; j < 4; ++j) { ks[r * 4 + j] = kr[j]; vs[r * 4 + j] = vr[j]; }
        }
        ull qa[8], qb[8];
        {
            const ull* q0 = (const ull*)(base + (64 + t) * 384 + h * HD);
            const ull* q1 = (const ull*)(base + t * 384 + h * HD);
#pragma unroll
            for (int j = 0; j < 8; ++j) { MUL2(qa[j], q0[j], C025); MUL2(qb[j], q1[j], C025); }
        }
        __syncthreads();

        const float* mk = g_maskT + (size_t)(b & 511) * 16384 + t;

        ull acca[8] = {}, accb[8] = {};
        float sma = 0.f, smb = 0.f;

        float fm[8];
#pragma unroll
        for (int j = 0; j < 8; ++j) fm[j] = mk[j * 128];

        for (int ch = 0; ch < 8; ++ch) {
            float nm[8];
            if (ch < 7) {
#pragma unroll
                for (int j = 0; j < 8; ++j) nm[j] = mk[(ch * 8 + 8 + j) * 128];
            }
#pragma unroll
            for (int j = 0; j < 8; ++j) {
                const int m = ch * 8 + j;
                ulonglong2 ka0 = ks[m * 4 + 0], ka1 = ks[m * 4 + 1];
                ulonglong2 ka2 = ks[m * 4 + 2], ka3 = ks[m * 4 + 3];
                ulonglong2 kb0 = ks[(64 + m) * 4 + 0], kb1 = ks[(64 + m) * 4 + 1];
                ulonglong2 kb2 = ks[(64 + m) * 4 + 2], kb3 = ks[(64 + m) * 4 + 3];
                ull da0 = 0, da1 = 0, db0 = 0, db1 = 0;
                FMA2(da0, qa[0], ka0.x); FMA2(da1, qa[1], ka0.y);
                FMA2(da0, qa[2], ka1.x); FMA2(da1, qa[3], ka1.y);
                FMA2(da0, qa[4], ka2.x); FMA2(da1, qa[5], ka2.y);
                FMA2(da0, qa[6], ka3.x); FMA2(da1, qa[7], ka3.y);
                FMA2(db0, qb[0], kb0.x); FMA2(db1, qb[1], kb0.y);
                FMA2(db0, qb[2], kb1.x); FMA2(db1, qb[3], kb1.y);
                FMA2(db0, qb[4], kb2.x); FMA2(db1, qb[5], kb2.y);
                FMA2(db0, qb[6], kb3.x); FMA2(db1, qb[7], kb3.y);
                ull ds; float lo, hi;
                ADD2(ds, da0, da1); UNPACKF2(lo, hi, ds);
                float sa = lo + hi + fm[j];
                ADD2(ds, db0, db1); UNPACKF2(lo, hi, ds);
                float sb = lo + hi + fm[j];
                float pa = __expf(sa), pb = __expf(sb);
                sma += pa; smb += pb;
                ull pa2, pb2; PACKF2(pa2, pa, pa); PACKF2(pb2, pb, pb);
                ulonglong2 va0 = vs[m * 4 + 0], va1 = vs[m * 4 + 1];
                ulonglong2 va2 = vs[m * 4 + 2], va3 = vs[m * 4 + 3];
                ulonglong2 vb0 = vs[(64 + m) * 4 + 0], vb1 = vs[(64 + m) * 4 + 1];
                ulonglong2 vb2 = vs[(64 + m) * 4 + 2], vb3 = vs[(64 + m) * 4 + 3];
                FMA2(acca[0], pa2, va0.x); FMA2(acca[1], pa2, va0.y);
                FMA2(acca[2], pa2, va1.x); FMA2(acca[3], pa2, va1.y);
                FMA2(acca[4], pa2, va2.x); FMA2(acca[5], pa2, va2.y);
                FMA2(acca[6], pa2, va3.x); FMA2(acca[7], pa2, va3.y);
                FMA2(accb[0], pb2, vb0.x); FMA2(accb[1], pb2, vb0.y);
                FMA2(accb[2], pb2, vb1.x); FMA2(accb[3], pb2, vb1.y);
                FMA2(accb[4], pb2, vb2.x); FMA2(accb[5], pb2, vb2.y);
                FMA2(accb[6], pb2, vb3.x); FMA2(accb[7], pb2, vb3.y);
            }
            if (ch < 7) {
#pragma unroll
                for (int j = 0; j < 8; ++j) fm[j] = nm[j];
            }
        }
        float ia = 1.f / sma, ib = 1.f / smb;
        float oa[16], ob[16];
#pragma unroll
        for (int j = 0; j < 8; ++j) {
            float lo, hi;
            UNPACKF2(lo, hi, acca[j]); oa[2 * j] = lo * ia; oa[2 * j + 1] = hi * ia;
            UNPACKF2(lo, hi, accb[j]); ob[2 * j] = lo * ib; ob[2 * j + 1] = hi * ib;
        }
        store_triplets16(g_concat3 + ((size_t)b * NTOK + t) * 768 + (h * HD) * 3, oa);
        store_triplets16(g_concat3 + ((size_t)b * NTOK + t + 64) * 768 + (h * HD) * 3, ob);
    }
}

// ---------------- launch ----------------------------------------------------
extern "C" void kernel_launch(void* const* d_in, const int* in_sizes, int n_in,
                              void* d_out, int out_size)
{
    const float* x         = (const float*)d_in[0];
    const float* mask      = (const float*)d_in[1];
    const float* w_self    = (const float*)d_in[2];
    const float* w_mut     = (const float*)d_in[3];
    const float* w_proj    = (const float*)d_in[4];
    const float* b_proj    = (const float*)d_in[5];
    const float* rpe_table = (const float*)d_in[6];
    const float* pe        = (const float*)d_in[7];
    const int*   rpe_index = (const int*)d_in[8];
    float* out = (float*)d_out;

    unsigned short *xs, *xpes, *cc, *ws, *wm, *wp;
    float *qs, *qm;
    cudaGetSymbolAddress((void**)&ws, g_ws3);
    cudaGetSymbolAddress((void**)&wm, g_wm3);
    cudaGetSymbolAddress((void**)&wp, g_wp3);
    cudaGetSymbolAddress((void**)&xs, g_xs3);
    cudaGetSymbolAddress((void**)&xpes, g_xpes3);
    cudaGetSymbolAddress((void**)&qs, g_qkv_self);
    cudaGetSymbolAddress((void**)&qm, g_qkv_mut);
    cudaGetSymbolAddress((void**)&cc, g_concat3);

    const int SMEM = 2 * NSTAGE * STAGE_ELEMS * (int)sizeof(__nv_bfloat16); // 110592
    cudaFuncSetAttribute(gemm_bf16<384, 384, false>,
                         cudaFuncAttributeMaxDynamicSharedMemorySize, SMEM);
    cudaFuncSetAttribute(gemm_bf16<768, 128, true>,
                         cudaFuncAttributeMaxDynamicSharedMemorySize, SMEM);

    // launch 1: all prep (weights, x-split, maskT + fused mbias)
    prep_all<<<16896, 256>>>(x, pe, w_self, w_mut, w_proj, mask, rpe_index, rpe_table);

    // launches 2,3: QKV GEMMs (K' = 384)
    gemm_bf16<384, 384, false><<<dim3(3, 1024), 256, SMEM>>>(
        (const __nv_bfloat16*)xs,   (const __nv_bfloat16*)ws, nullptr, qs);
    gemm_bf16<384, 384, false><<<dim3(3, 1024), 256, SMEM>>>(
        (const __nv_bfloat16*)xpes, (const __nv_bfloat16*)wm, nullptr, qm);

    // launch 4: merged attention  (<- ncu capture slot)
    attn_all<<<dim3(WB, 16), 64>>>();

    // launch 5: projection (K' = 768)
    gemm_bf16<768, 128, true><<<dim3(1, 1024), 256, SMEM>>>(
        (const __nv_bfloat16*)cc, (const __nv_bfloat16*)wp, b_proj, out);
}